// round 6
// baseline (speedup 1.0000x reference)
#include <cuda_runtime.h>
#include <stdint.h>

// YOLACT-550 Fast-NMS, GB300 sm_103a — round 5
// Phase-split design:
//   K0: zero per-row counters
//   K1: grid-stride streaming threshold filter -> global candidate lists
//   K2: per-row sort + division-free Fast-NMS + pack (exact bisection fallback)

#define NB   16
#define NC   80
#define NROW (NB*NC)         // 1280
#define NN   19248
#define NV4  4812            // NN/4
#define KTOP 200
#define CAP  512
#define NT   256
#define NWARP (NT/32)
#define GRID1 2432           // 16 CTAs per SM-wave for the filter

// global scratch (allocation-free requirement -> __device__ arrays)
__device__ unsigned long long g_cand[(size_t)NROW * CAP];   // 5 MB
__device__ int                g_cnt[NROW];

__device__ __forceinline__ unsigned long long mk_key(uint32_t v, uint32_t idx) {
    // descending value, ascending index on ties (matches jax.lax.top_k)
    return ((unsigned long long)v << 32) | (unsigned long long)(0xFFFFFFFFu - idx);
}

// ---------------------------------------------------------------- K0: zero
__global__ void zero_counters() {
    int i = blockIdx.x * blockDim.x + threadIdx.x;
    if (i < NROW) g_cnt[i] = 0;
}

// ---------------------------------------------------------------- K1: filter
__global__ __launch_bounds__(NT, 16)
void filter_kernel(const float* __restrict__ scores)
{
    // Scores are non-negative floats: raw-bit unsigned compare == float compare.
    const uint32_t T = __float_as_uint(0.98337f);   // E[count]~320/row, sigma~18
    const uint4* s4 = reinterpret_cast<const uint4*>(scores);
    const int total = NROW * NV4;                   // 6,159,360 uint4
    const int stride = GRID1 * NT;

    for (int i = blockIdx.x * NT + threadIdx.x; i < total; i += stride) {
        uint4 v = __ldcs(s4 + i);
        uint32_t mx = max(max(v.x, v.y), max(v.z, v.w));
        if (mx >= T) {                              // rare: ~6.4% of uint4s
            int row = i / NV4;                      // const-div -> mul-high
            int rem = i - row * NV4;
            uint32_t base = (uint32_t)rem * 4u;
            uint32_t vals[4] = {v.x, v.y, v.z, v.w};
            #pragma unroll
            for (int j = 0; j < 4; ++j) {
                if (vals[j] >= T) {
                    int p = atomicAdd(&g_cnt[row], 1);
                    if (p < CAP)
                        g_cand[(size_t)row * CAP + p] = mk_key(vals[j], base + j);
                }
            }
        }
    }
}

// ---------------------------------------------------------------- K2: NMS
__global__ __launch_bounds__(NT, 8)
void nms_kernel(const float* __restrict__ boxes_raw,
                const float* __restrict__ scores,
                float* __restrict__ out)
{
    __shared__ unsigned long long cand[CAP];   // keys; reused as output stage
    __shared__ float4   sboxv[KTOP];
    __shared__ float    sar[KTOP];
    __shared__ uint32_t keepf[KTOP];
    __shared__ uint32_t red[32];
    __shared__ int scnt;

    const int tid  = threadIdx.x;
    const int lane = tid & 31;
    const int wid  = tid >> 5;
    const int bc   = blockIdx.x;               // b*NC + c
    const int b    = bc / NC;

    int M = g_cnt[bc];

    if (M >= KTOP && M <= CAP) {
        // ---- load compact candidate list (2 keys/thread) ----
        const unsigned long long* src = g_cand + (size_t)bc * CAP;
        #pragma unroll
        for (int i = tid; i < CAP; i += NT)
            cand[i] = (i < M) ? src[i] : 0ull;
        __syncthreads();
    } else {
        // ---- exact fallback: full-row bisection (statistically never taken) --
        const uint4* srow = reinterpret_cast<const uint4*>(scores) + (size_t)bc * NV4;
        uint32_t mymax = 0u;
        for (int i = tid; i < NV4; i += NT) {
            uint4 v = srow[i];
            mymax = max(mymax, max(max(v.x, v.y), max(v.z, v.w)));
        }
        #pragma unroll
        for (int o = 16; o; o >>= 1)
            mymax = max(mymax, __shfl_xor_sync(0xFFFFFFFFu, mymax, o));
        if (lane == 0) red[wid] = mymax;
        __syncthreads();
        if (tid == 0) {
            uint32_t mm = red[0];
            for (int w = 1; w < NWARP; ++w) mm = max(mm, red[w]);
            red[16] = mm;
        }
        __syncthreads();

        uint32_t lo = 0u, hi = red[16];
        uint32_t T = 0u;
        int bestGe = NN;
        for (int it = 0; it < 34 && lo <= hi; ++it) {
            uint32_t t = lo + ((hi - lo) >> 1);
            int c = 0;
            for (int i = tid; i < NV4; i += NT) {
                uint4 v = srow[i];
                c += (v.x >= t) + (v.y >= t) + (v.z >= t) + (v.w >= t);
            }
            #pragma unroll
            for (int o = 16; o; o >>= 1) c += __shfl_down_sync(0xFFFFFFFFu, c, o);
            __syncthreads();
            if (lane == 0) red[wid] = (uint32_t)c;
            __syncthreads();
            if (tid == 0) {
                int s = 0;
                for (int w = 0; w < NWARP; ++w) s += (int)red[w];
                red[17] = (uint32_t)s;
            }
            __syncthreads();
            int ge = (int)red[17];
            if (ge >= KTOP) {
                if (ge < bestGe) { bestGe = ge; T = t; }
                if (ge <= CAP) break;
                lo = t + 1;
            } else {
                if (t == 0) break;
                hi = t - 1;
            }
        }
        __syncthreads();
        if (tid == 0) scnt = 0;
        __syncthreads();
        for (int i = tid; i < NV4; i += NT) {
            uint4 v = srow[i];
            if (max(max(v.x, v.y), max(v.z, v.w)) >= T) {
                uint32_t vals[4] = {v.x, v.y, v.z, v.w};
                #pragma unroll
                for (int j = 0; j < 4; ++j) {
                    if (vals[j] >= T) {
                        int p = atomicAdd(&scnt, 1);
                        if (p < CAP) cand[p] = mk_key(vals[j], (uint32_t)(4 * i + j));
                    }
                }
            }
        }
        __syncthreads();
        M = min(scnt, CAP);
        for (int i = M + tid; i < CAP; i += NT) cand[i] = 0ull;
        __syncthreads();
    }

    // ---------------- Bitonic sort, descending, S=512, 1 CE/thread/round ------
    #pragma unroll 1
    for (int k = 2; k <= CAP; k <<= 1) {
        #pragma unroll 1
        for (int j = k >> 1; j > 0; j >>= 1) {
            int i   = 2 * tid - (tid & (j - 1));
            int ixj = i + j;
            unsigned long long a  = cand[i];
            unsigned long long c2 = cand[ixj];
            bool desc = ((i & k) == 0);
            if ((a < c2) == desc) { cand[i] = c2; cand[ixj] = a; }
            __syncthreads();
        }
    }

    // ---------------- Gather + decode boxes -----------------------------------
    float x1 = 0.f, y1v = 0.f, x2 = 0.f, y2v = 0.f, sc = 0.f;
    if (tid < KTOP) {
        unsigned long long key = cand[tid];
        uint32_t idx = 0xFFFFFFFFu - (uint32_t)(key & 0xFFFFFFFFull);
        sc = __uint_as_float((uint32_t)(key >> 32));
        float4 rb = __ldg(reinterpret_cast<const float4*>(boxes_raw) + (size_t)b * NN + idx);
        float w  = rb.z * 0.5f + 1e-2f;
        float h  = rb.w * 0.5f + 1e-2f;
        float hw = 0.5f * w, hh = 0.5f * h;
        x1  = rb.x - hw;  x2  = rb.x + hw;
        y1v = rb.y - hh;  y2v = rb.y + hh;
        sboxv[tid] = make_float4(x1, y1v, x2, y2v);
        sar[tid]   = (x2 - x1) * (y2v - y1v);   // area from corners (match ref)
    }
    __syncthreads();

    // ---------------- Warp-balanced division-free suppression -----------------
    // iou <= 0.5  <=>  2*inter <= union  <=>  3*inter <= area_i + area_j
    for (int j = wid; j < KTOP; j += NWARP) {
        float4 bj = sboxv[j];
        float  aj = sar[j];
        bool sup = false;
        for (int i = lane; i < j; i += 32) {
            float4 bi = sboxv[i];
            float iw = fminf(bj.z, bi.z) - fmaxf(bj.x, bi.x);
            float ih = fminf(bj.w, bi.w) - fmaxf(bj.y, bi.y);
            iw = fmaxf(iw, 0.f);
            ih = fmaxf(ih, 0.f);
            sup = sup || (3.0f * (iw * ih) > aj + sar[i]);
        }
        sup = __any_sync(0xFFFFFFFFu, sup);
        if (lane == 0) keepf[j] = sup ? 0u : 1u;
    }
    __syncthreads();                            // guards cand reuse below

    // ---------------- Stage + coalesced output write --------------------------
    float* stage = reinterpret_cast<float*>(cand);
    if (tid < KTOP) {
        float osc = (keepf[tid] && sc > 0.05f) ? sc : 0.f;
        stage[tid * 5 + 0] = osc;
        stage[tid * 5 + 1] = x1;
        stage[tid * 5 + 2] = y1v;
        stage[tid * 5 + 3] = x2;
        stage[tid * 5 + 4] = y2v;
    }
    __syncthreads();

    {   // 1000 floats = 250 uint4 per row
        uint4* dst = reinterpret_cast<uint4*>(out + (size_t)bc * (KTOP * 5));
        const uint4* src = reinterpret_cast<const uint4*>(stage);
        if (tid < 250) dst[tid] = src[tid];
    }
}

extern "C" void kernel_launch(void* const* d_in, const int* in_sizes, int n_in,
                              void* d_out, int out_size)
{
    const float* boxes  = (const float*)d_in[0];
    const float* scores = (const float*)d_in[1];
    if (n_in >= 2 && in_sizes[0] > in_sizes[1]) {   // defensive order check
        boxes  = (const float*)d_in[1];
        scores = (const float*)d_in[0];
    }
    (void)out_size;

    zero_counters<<<(NROW + NT - 1) / NT, NT>>>();
    filter_kernel<<<GRID1, NT>>>(scores);
    nms_kernel<<<NROW, NT>>>(boxes, scores, (float*)d_out);
}

// round 7
// speedup vs baseline: 1.0824x; 1.0824x over previous
#include <cuda_runtime.h>
#include <stdint.h>

// YOLACT-550 Fast-NMS, GB300 sm_103a — round 6
// Two-kernel split (R5 regression root-caused to a launch_bounds-induced
// register spill in the filter; fixed here):
//   K1: bandwidth-bound batched streaming filter -> global candidate lists
//   K2: per-row sort + division-free Fast-NMS + pack; re-zeroes counters
//       (g_cnt starts zero-initialized, so state is identical every call)

#define NB   16
#define NC   80
#define NROW (NB*NC)         // 1280
#define NN   19248
#define NV4  4812            // NN/4
#define KTOP 200
#define CAP  512
#define NT   256
#define NWARP (NT/32)

// exact partition: 1203 CTAs * 5 iters * 4 loads * 256 threads = 6,159,360 uint4
#define GRID_F 1203
#define ITER_F 5

// global scratch (allocation-free rule -> __device__ arrays; zero-initialized)
__device__ unsigned long long g_cand[(size_t)NROW * CAP];   // 5 MB
__device__ int                g_cnt[NROW];

__device__ __forceinline__ unsigned long long mk_key(uint32_t v, uint32_t idx) {
    // descending value, ascending index on ties (matches jax.lax.top_k)
    return ((unsigned long long)v << 32) | (unsigned long long)(0xFFFFFFFFu - idx);
}

// ---------------------------------------------------------------- K1: filter
__device__ __forceinline__ void push_hit(int row, uint32_t val, uint32_t idx) {
    int p = atomicAdd(&g_cnt[row], 1);
    if (p < CAP) g_cand[(size_t)row * CAP + p] = mk_key(val, idx);
}

__device__ __forceinline__ void process_u4(uint4 v, uint32_t m, int i, uint32_t T) {
    if (m >= T) {                       // per-thread prob ~6.4%
        int row = i / NV4;              // const-div -> mulhi
        uint32_t base = (uint32_t)(i - row * NV4) * 4u;
        if (v.x >= T) push_hit(row, v.x, base + 0u);
        if (v.y >= T) push_hit(row, v.y, base + 1u);
        if (v.z >= T) push_hit(row, v.z, base + 2u);
        if (v.w >= T) push_hit(row, v.w, base + 3u);
    }
}

__global__ __launch_bounds__(NT, 6)
void filter_kernel(const float* __restrict__ scores)
{
    // Scores are non-negative floats: raw-bit unsigned compare == float compare.
    const uint32_t T = __float_as_uint(0.98337f);   // E[count]~320/row, sigma~18
    const uint4* s4 = reinterpret_cast<const uint4*>(scores);
    const int tid = threadIdx.x;

    #pragma unroll 1
    for (int it = 0; it < ITER_F; ++it) {
        int base = (it * GRID_F + blockIdx.x) * (4 * NT);
        int i0 = base + 0 * NT + tid;
        int i1 = base + 1 * NT + tid;
        int i2 = base + 2 * NT + tid;
        int i3 = base + 3 * NT + tid;
        uint4 v0 = __ldcs(s4 + i0);     // 4 independent LDG.128 -> MLP=4
        uint4 v1 = __ldcs(s4 + i1);
        uint4 v2 = __ldcs(s4 + i2);
        uint4 v3 = __ldcs(s4 + i3);
        uint32_t m0 = max(max(v0.x, v0.y), max(v0.z, v0.w));
        uint32_t m1 = max(max(v1.x, v1.y), max(v1.z, v1.w));
        uint32_t m2 = max(max(v2.x, v2.y), max(v2.z, v2.w));
        uint32_t m3 = max(max(v3.x, v3.y), max(v3.z, v3.w));
        if (max(max(m0, m1), max(m2, m3)) >= T) {   // per-thread prob ~23%
            process_u4(v0, m0, i0, T);
            process_u4(v1, m1, i1, T);
            process_u4(v2, m2, i2, T);
            process_u4(v3, m3, i3, T);
        }
    }
}

// ---------------------------------------------------------------- K2: NMS
__global__ __launch_bounds__(NT, 6)
void nms_kernel(const float* __restrict__ boxes_raw,
                const float* __restrict__ scores,
                float* __restrict__ out)
{
    __shared__ unsigned long long cand[CAP];   // keys; reused as output stage
    __shared__ float4   sboxv[KTOP];
    __shared__ float    sar[KTOP];
    __shared__ uint32_t keepf[KTOP];
    __shared__ uint32_t red[32];
    __shared__ int scnt;

    const int tid  = threadIdx.x;
    const int lane = tid & 31;
    const int wid  = tid >> 5;
    const int bc   = blockIdx.x;               // b*NC + c
    const int b    = bc / NC;

    int M = g_cnt[bc];                          // all threads read
    __syncthreads();                            // reads complete before reset
    if (tid == 0) g_cnt[bc] = 0;                // restore state for next call

    if (M >= KTOP && M <= CAP) {
        const unsigned long long* src = g_cand + (size_t)bc * CAP;
        #pragma unroll
        for (int i = tid; i < CAP; i += NT)
            cand[i] = (i < M) ? src[i] : 0ull;
        __syncthreads();
    } else {
        // ---- exact fallback: full-row bisection (statistically never taken) --
        const uint4* srow = reinterpret_cast<const uint4*>(scores) + (size_t)bc * NV4;
        uint32_t mymax = 0u;
        for (int i = tid; i < NV4; i += NT) {
            uint4 v = srow[i];
            mymax = max(mymax, max(max(v.x, v.y), max(v.z, v.w)));
        }
        #pragma unroll
        for (int o = 16; o; o >>= 1)
            mymax = max(mymax, __shfl_xor_sync(0xFFFFFFFFu, mymax, o));
        if (lane == 0) red[wid] = mymax;
        __syncthreads();
        if (tid == 0) {
            uint32_t mm = red[0];
            for (int w = 1; w < NWARP; ++w) mm = max(mm, red[w]);
            red[16] = mm;
        }
        __syncthreads();

        uint32_t lo = 0u, hi = red[16];
        uint32_t T = 0u;
        int bestGe = NN;
        for (int it = 0; it < 34 && lo <= hi; ++it) {
            uint32_t t = lo + ((hi - lo) >> 1);
            int c = 0;
            for (int i = tid; i < NV4; i += NT) {
                uint4 v = srow[i];
                c += (v.x >= t) + (v.y >= t) + (v.z >= t) + (v.w >= t);
            }
            #pragma unroll
            for (int o = 16; o; o >>= 1) c += __shfl_down_sync(0xFFFFFFFFu, c, o);
            __syncthreads();
            if (lane == 0) red[wid] = (uint32_t)c;
            __syncthreads();
            if (tid == 0) {
                int s = 0;
                for (int w = 0; w < NWARP; ++w) s += (int)red[w];
                red[17] = (uint32_t)s;
            }
            __syncthreads();
            int ge = (int)red[17];
            if (ge >= KTOP) {
                if (ge < bestGe) { bestGe = ge; T = t; }
                if (ge <= CAP) break;
                lo = t + 1;
            } else {
                if (t == 0) break;
                hi = t - 1;
            }
        }
        __syncthreads();
        if (tid == 0) scnt = 0;
        __syncthreads();
        for (int i = tid; i < NV4; i += NT) {
            uint4 v = srow[i];
            if (max(max(v.x, v.y), max(v.z, v.w)) >= T) {
                uint32_t vals[4] = {v.x, v.y, v.z, v.w};
                #pragma unroll
                for (int j = 0; j < 4; ++j) {
                    if (vals[j] >= T) {
                        int p = atomicAdd(&scnt, 1);
                        if (p < CAP) cand[p] = mk_key(vals[j], (uint32_t)(4 * i + j));
                    }
                }
            }
        }
        __syncthreads();
        M = min(scnt, CAP);
        for (int i = M + tid; i < CAP; i += NT) cand[i] = 0ull;
        __syncthreads();
    }

    // ---------------- Bitonic sort, descending, S=512, 1 CE/thread/round ------
    #pragma unroll 1
    for (int k = 2; k <= CAP; k <<= 1) {
        #pragma unroll 1
        for (int j = k >> 1; j > 0; j >>= 1) {
            int i   = 2 * tid - (tid & (j - 1));
            int ixj = i + j;
            unsigned long long a  = cand[i];
            unsigned long long c2 = cand[ixj];
            bool desc = ((i & k) == 0);
            if ((a < c2) == desc) { cand[i] = c2; cand[ixj] = a; }
            __syncthreads();
        }
    }

    // ---------------- Gather + decode boxes -----------------------------------
    float x1 = 0.f, y1v = 0.f, x2 = 0.f, y2v = 0.f, sc = 0.f;
    if (tid < KTOP) {
        unsigned long long key = cand[tid];
        uint32_t idx = 0xFFFFFFFFu - (uint32_t)(key & 0xFFFFFFFFull);
        sc = __uint_as_float((uint32_t)(key >> 32));
        float4 rb = __ldg(reinterpret_cast<const float4*>(boxes_raw) + (size_t)b * NN + idx);
        float w  = rb.z * 0.5f + 1e-2f;
        float h  = rb.w * 0.5f + 1e-2f;
        float hw = 0.5f * w, hh = 0.5f * h;
        x1  = rb.x - hw;  x2  = rb.x + hw;
        y1v = rb.y - hh;  y2v = rb.y + hh;
        sboxv[tid] = make_float4(x1, y1v, x2, y2v);
        sar[tid]   = (x2 - x1) * (y2v - y1v);   // area from corners (match ref)
    }
    __syncthreads();

    // ---------------- Warp-balanced division-free suppression -----------------
    // iou <= 0.5  <=>  2*inter <= union  <=>  3*inter <= area_i + area_j
    for (int j = wid; j < KTOP; j += NWARP) {
        float4 bj = sboxv[j];
        float  aj = sar[j];
        bool sup = false;
        for (int i = lane; i < j; i += 32) {
            float4 bi = sboxv[i];
            float iw = fminf(bj.z, bi.z) - fmaxf(bj.x, bi.x);
            float ih = fminf(bj.w, bi.w) - fmaxf(bj.y, bi.y);
            iw = fmaxf(iw, 0.f);
            ih = fmaxf(ih, 0.f);
            sup = sup || (3.0f * (iw * ih) > aj + sar[i]);
        }
        sup = __any_sync(0xFFFFFFFFu, sup);
        if (lane == 0) keepf[j] = sup ? 0u : 1u;
    }
    __syncthreads();                            // guards cand reuse below

    // ---------------- Stage + coalesced output write --------------------------
    float* stage = reinterpret_cast<float*>(cand);
    if (tid < KTOP) {
        float osc = (keepf[tid] && sc > 0.05f) ? sc : 0.f;
        stage[tid * 5 + 0] = osc;
        stage[tid * 5 + 1] = x1;
        stage[tid * 5 + 2] = y1v;
        stage[tid * 5 + 3] = x2;
        stage[tid * 5 + 4] = y2v;
    }
    __syncthreads();

    {   // 1000 floats = 250 uint4 per row
        uint4* dst = reinterpret_cast<uint4*>(out + (size_t)bc * (KTOP * 5));
        const uint4* src = reinterpret_cast<const uint4*>(stage);
        if (tid < 250) dst[tid] = src[tid];
    }
}

extern "C" void kernel_launch(void* const* d_in, const int* in_sizes, int n_in,
                              void* d_out, int out_size)
{
    const float* boxes  = (const float*)d_in[0];
    const float* scores = (const float*)d_in[1];
    if (n_in >= 2 && in_sizes[0] > in_sizes[1]) {   // defensive order check
        boxes  = (const float*)d_in[1];
        scores = (const float*)d_in[0];
    }
    (void)out_size;

    filter_kernel<<<GRID_F, NT>>>(scores);
    nms_kernel<<<NROW, NT>>>(boxes, scores, (float*)d_out);
}

// round 8
// speedup vs baseline: 1.6682x; 1.5412x over previous
#include <cuda_runtime.h>
#include <stdint.h>

// YOLACT-550 Fast-NMS, GB300 sm_103a — round 7
// Fused single kernel (R4 base, best known) with the 512-key bitonic sort
// rebuilt as a hybrid register/shuffle sort: 39/45 rounds barrier-free in
// registers, only 6 cross-warp rounds via smem.

#define NB   16
#define NC   80
#define NN   19248
#define NV4  4812            // NN/4
#define KTOP 200
#define CAP  512
#define NT   256
#define NWARP (NT/32)

__device__ __forceinline__ unsigned long long mk_key(uint32_t v, uint32_t idx) {
    // descending value, ascending index on ties (matches jax.lax.top_k)
    return ((unsigned long long)v << 32) | (unsigned long long)(0xFFFFFFFFu - idx);
}

__device__ __forceinline__ unsigned long long shfl_xor_u64(unsigned long long v, int m) {
    uint32_t lo = (uint32_t)(v & 0xFFFFFFFFull);
    uint32_t hi = (uint32_t)(v >> 32);
    lo = __shfl_xor_sync(0xFFFFFFFFu, lo, m);
    hi = __shfl_xor_sync(0xFFFFFFFFu, hi, m);
    return ((unsigned long long)hi << 32) | (unsigned long long)lo;
}

// register compare-exchange across lanes (partner = lane ^ j), j <= 16
__device__ __forceinline__ void ce_reg(unsigned long long& v, int i, int j, int k) {
    unsigned long long o = shfl_xor_u64(v, j);
    bool keep_max = (((i & k) == 0) == ((i & j) == 0));
    if ((o > v) == keep_max) v = o;      // keep_max ? max(v,o) : min(v,o)
}

__global__ __launch_bounds__(NT, 6)
void fastnms_kernel(const float* __restrict__ boxes_raw,
                    const float* __restrict__ scores,
                    float* __restrict__ out)
{
    __shared__ unsigned long long cand[CAP];   // keys; reused as output stage
    __shared__ float4   sboxv[KTOP];
    __shared__ float    sar[KTOP];
    __shared__ uint32_t keepf[KTOP];
    __shared__ uint32_t red[32];
    __shared__ int scnt;

    const int tid  = threadIdx.x;
    const int lane = tid & 31;
    const int wid  = tid >> 5;
    const int bc   = blockIdx.x;               // b*NC + c
    const int b    = bc / NC;

    const uint4* srow = reinterpret_cast<const uint4*>(scores) + (size_t)bc * NV4;

    // ---------------- 1. Compare-only streaming scan at statistical threshold --
    // Scores are non-negative floats: raw-bit unsigned compare == float compare.
    uint32_t T = __float_as_uint(0.98337f);    // E[count] ~= 320, sigma ~= 18

    if (tid == 0) scnt = 0;
    __syncthreads();

    #pragma unroll 4
    for (int i = tid; i < NV4; i += NT) {
        uint4 v = __ldcs(srow + i);            // streaming: single-use data
        if ((v.x >= T) + (v.y >= T) + (v.z >= T) + (v.w >= T)) {  // rare
            uint32_t vals[4] = {v.x, v.y, v.z, v.w};
            #pragma unroll
            for (int j = 0; j < 4; ++j) {
                if (vals[j] >= T) {
                    int p = atomicAdd(&scnt, 1);
                    if (p < CAP) cand[p] = mk_key(vals[j], (uint32_t)(4 * i + j));
                }
            }
        }
    }
    __syncthreads();
    int M = scnt;

    // ---------------- 2. Exact fallback (statistically never taken) ------------
    if (M < KTOP || M > CAP) {
        uint32_t mymax = 0u;
        for (int i = tid; i < NV4; i += NT) {
            uint4 v = srow[i];
            mymax = max(mymax, max(max(v.x, v.y), max(v.z, v.w)));
        }
        #pragma unroll
        for (int o = 16; o; o >>= 1)
            mymax = max(mymax, __shfl_xor_sync(0xFFFFFFFFu, mymax, o));
        if (lane == 0) red[wid] = mymax;
        __syncthreads();
        if (tid == 0) {
            uint32_t mm = red[0];
            for (int w = 1; w < NWARP; ++w) mm = max(mm, red[w]);
            red[16] = mm;
        }
        __syncthreads();

        uint32_t lo = 0u, hi = red[16];
        T = 0u;
        int bestGe = NN;
        for (int it = 0; it < 34 && lo <= hi; ++it) {
            uint32_t t = lo + ((hi - lo) >> 1);
            int c = 0;
            for (int i = tid; i < NV4; i += NT) {
                uint4 v = srow[i];
                c += (v.x >= t) + (v.y >= t) + (v.z >= t) + (v.w >= t);
            }
            #pragma unroll
            for (int o = 16; o; o >>= 1) c += __shfl_down_sync(0xFFFFFFFFu, c, o);
            __syncthreads();
            if (lane == 0) red[wid] = (uint32_t)c;
            __syncthreads();
            if (tid == 0) {
                int s = 0;
                for (int w = 0; w < NWARP; ++w) s += (int)red[w];
                red[17] = (uint32_t)s;
            }
            __syncthreads();
            int ge = (int)red[17];
            if (ge >= KTOP) {
                if (ge < bestGe) { bestGe = ge; T = t; }
                if (ge <= CAP) break;
                lo = t + 1;
            } else {
                if (t == 0) break;
                hi = t - 1;
            }
        }

        __syncthreads();
        if (tid == 0) scnt = 0;
        __syncthreads();
        for (int i = tid; i < NV4; i += NT) {
            uint4 v = srow[i];
            if (max(max(v.x, v.y), max(v.z, v.w)) >= T) {
                uint32_t vals[4] = {v.x, v.y, v.z, v.w};
                #pragma unroll
                for (int j = 0; j < 4; ++j) {
                    if (vals[j] >= T) {
                        int p = atomicAdd(&scnt, 1);
                        if (p < CAP) cand[p] = mk_key(vals[j], (uint32_t)(4 * i + j));
                    }
                }
            }
        }
        __syncthreads();
        M = min(scnt, CAP);
    }

    // ---------------- 3. Hybrid bitonic sort, descending, S=512 ----------------
    // Each thread holds 2 keys in registers: a = elem 64*wid+lane, b = +32.
    for (int i = M + tid; i < CAP; i += NT) cand[i] = 0ull;   // pad
    __syncthreads();

    const int ia = 64 * wid + lane;
    const int ib = ia + 32;
    unsigned long long a = cand[ia];
    unsigned long long bkey = cand[ib];

    #pragma unroll 1
    for (int k = 2; k <= CAP; k <<= 1) {
        int j = k >> 1;
        // cross-warp rounds (j >= 64): via smem, 2 barriers each (6 total rounds)
        #pragma unroll 1
        for (; j >= 64; j >>= 1) {
            __syncthreads();
            cand[ia] = a;  cand[ib] = bkey;
            __syncthreads();
            unsigned long long pa = cand[ia ^ j];
            unsigned long long pb = cand[ib ^ j];
            bool kma = (((ia & k) == 0) == ((ia & j) == 0));
            bool kmb = (((ib & k) == 0) == ((ib & j) == 0));
            if ((pa > a)    == kma) a    = pa;
            if ((pb > bkey) == kmb) bkey = pb;
        }
        // j == 32: partner is the other register of the SAME thread
        if (j == 32) {
            bool desc = ((ia & k) == 0);        // k >= 64 here: same for ia, ib
            unsigned long long mx = (a > bkey) ? a : bkey;
            unsigned long long mn = (a > bkey) ? bkey : a;
            a    = desc ? mx : mn;
            bkey = desc ? mn : mx;
            j >>= 1;
        }
        // j <= 16: lane-shuffle rounds, barrier-free
        #pragma unroll 1
        for (; j >= 1; j >>= 1) {
            ce_reg(a,    ia, j, k);
            ce_reg(bkey, ib, j, k);
        }
    }
    __syncthreads();
    cand[ia] = a;  cand[ib] = bkey;
    __syncthreads();

    // ---------------- 4. Gather + decode boxes ---------------------------------
    float x1 = 0.f, y1v = 0.f, x2 = 0.f, y2v = 0.f, sc = 0.f;
    if (tid < KTOP) {
        unsigned long long key = cand[tid];
        uint32_t idx = 0xFFFFFFFFu - (uint32_t)(key & 0xFFFFFFFFull);
        sc = __uint_as_float((uint32_t)(key >> 32));
        float4 rb = __ldg(reinterpret_cast<const float4*>(boxes_raw) + (size_t)b * NN + idx);
        float w  = rb.z * 0.5f + 1e-2f;
        float h  = rb.w * 0.5f + 1e-2f;
        float hw = 0.5f * w, hh = 0.5f * h;
        x1  = rb.x - hw;  x2  = rb.x + hw;
        y1v = rb.y - hh;  y2v = rb.y + hh;
        sboxv[tid] = make_float4(x1, y1v, x2, y2v);
        sar[tid]   = (x2 - x1) * (y2v - y1v);   // area from corners (match ref)
    }
    __syncthreads();

    // ---------------- 5. Warp-balanced division-free suppression ---------------
    // iou <= 0.5  <=>  2*inter <= union  <=>  3*inter <= area_i + area_j
    for (int j = wid; j < KTOP; j += NWARP) {
        float4 bj = sboxv[j];
        float  aj = sar[j];
        bool sup = false;
        for (int i = lane; i < j; i += 32) {
            float4 bi = sboxv[i];
            float iw = fminf(bj.z, bi.z) - fmaxf(bj.x, bi.x);
            float ih = fminf(bj.w, bi.w) - fmaxf(bj.y, bi.y);
            iw = fmaxf(iw, 0.f);
            ih = fmaxf(ih, 0.f);
            sup = sup || (3.0f * (iw * ih) > aj + sar[i]);
        }
        sup = __any_sync(0xFFFFFFFFu, sup);
        if (lane == 0) keepf[j] = sup ? 0u : 1u;
    }
    __syncthreads();                            // guards cand reuse below

    // ---------------- 6. Stage + coalesced output write ------------------------
    float* stage = reinterpret_cast<float*>(cand);   // 4KB >= 200*5*4B
    if (tid < KTOP) {
        float osc = (keepf[tid] && sc > 0.05f) ? sc : 0.f;
        stage[tid * 5 + 0] = osc;
        stage[tid * 5 + 1] = x1;
        stage[tid * 5 + 2] = y1v;
        stage[tid * 5 + 3] = x2;
        stage[tid * 5 + 4] = y2v;
    }
    __syncthreads();

    {   // 1000 floats = 250 uint4 per row
        uint4* dst = reinterpret_cast<uint4*>(out + (size_t)bc * (KTOP * 5));
        const uint4* src = reinterpret_cast<const uint4*>(stage);
        if (tid < 250) dst[tid] = src[tid];
    }
}

extern "C" void kernel_launch(void* const* d_in, const int* in_sizes, int n_in,
                              void* d_out, int out_size)
{
    const float* boxes  = (const float*)d_in[0];
    const float* scores = (const float*)d_in[1];
    if (n_in >= 2 && in_sizes[0] > in_sizes[1]) {   // defensive order check
        boxes  = (const float*)d_in[1];
        scores = (const float*)d_in[0];
    }
    (void)out_size;
    fastnms_kernel<<<NB * NC, NT>>>(boxes, scores, (float*)d_out);
}

// round 9
// speedup vs baseline: 1.7724x; 1.0625x over previous
#include <cuda_runtime.h>
#include <stdint.h>

// YOLACT-550 Fast-NMS, GB300 sm_103a — round 8
// Fused kernel; the 512-key bitonic sort is replaced by an exact counting
// sort: bucket by value (uniform distribution), guarded max-load <= 8,
// stable scatter, 8 odd-even cleanup passes with the full tie-breaking
// comparator. Bitonic retained only as a guarded fallback.

#define NB   16
#define NC   80
#define NN   19248
#define NV4  4812            // NN/4
#define KTOP 200
#define CAP  512
#define NT   256
#define NWARP (NT/32)

#define NBUCK  2560          // buckets; NBUCK << BSHIFT covers delta range
#define BSHIFT 7
#define BPT    (NBUCK/NT)    // 10 buckets per thread

__device__ __forceinline__ unsigned long long mk_key(uint32_t v, uint32_t idx) {
    // descending value, ascending index on ties (matches jax.lax.top_k)
    return ((unsigned long long)v << 32) | (unsigned long long)(0xFFFFFFFFu - idx);
}

__device__ __forceinline__ int bucket_of(uint32_t valbits) {
    int d = (int)(0x3F800000u - valbits);        // smaller delta = larger value
    d = (d < 0) ? 0 : d;
    int b = d >> BSHIFT;
    return (b > NBUCK - 1) ? (NBUCK - 1) : b;    // clamp keeps monotonicity
}

__global__ __launch_bounds__(NT, 6)
void fastnms_kernel(const float* __restrict__ boxes_raw,
                    const float* __restrict__ scores,
                    float* __restrict__ out)
{
    __shared__ unsigned long long cand[CAP];     // collected keys; also stage
    __shared__ unsigned long long dst[CAP];      // sorted keys (bucket path)
    __shared__ uint32_t counts[NBUCK];
    __shared__ float4   sboxv[KTOP];
    __shared__ float    sar[KTOP];
    __shared__ uint32_t keepf[KTOP];
    __shared__ uint32_t red[32];
    __shared__ int scnt;

    const int tid  = threadIdx.x;
    const int lane = tid & 31;
    const int wid  = tid >> 5;
    const int bc   = blockIdx.x;                 // b*NC + c
    const int b    = bc / NC;

    const uint4* srow = reinterpret_cast<const uint4*>(scores) + (size_t)bc * NV4;

    // ---------------- 1. Compare-only streaming scan at statistical threshold --
    // Scores are non-negative floats: raw-bit unsigned compare == float compare.
    uint32_t T = __float_as_uint(0.98337f);      // E[count] ~= 320, sigma ~= 18

    if (tid == 0) scnt = 0;
    #pragma unroll
    for (int t = 0; t < BPT; ++t) counts[tid + t * NT] = 0u;   // zero buckets
    __syncthreads();

    #pragma unroll 4
    for (int i = tid; i < NV4; i += NT) {
        uint4 v = __ldcs(srow + i);              // streaming: single-use data
        if ((v.x >= T) + (v.y >= T) + (v.z >= T) + (v.w >= T)) {   // rare
            uint32_t vals[4] = {v.x, v.y, v.z, v.w};
            #pragma unroll
            for (int j = 0; j < 4; ++j) {
                if (vals[j] >= T) {
                    int p = atomicAdd(&scnt, 1);
                    if (p < CAP) cand[p] = mk_key(vals[j], (uint32_t)(4 * i + j));
                }
            }
        }
    }
    __syncthreads();
    int M = scnt;

    // ---------------- 2. Exact fallback (statistically never taken) ------------
    if (M < KTOP || M > CAP) {
        uint32_t mymax = 0u;
        for (int i = tid; i < NV4; i += NT) {
            uint4 v = srow[i];
            mymax = max(mymax, max(max(v.x, v.y), max(v.z, v.w)));
        }
        #pragma unroll
        for (int o = 16; o; o >>= 1)
            mymax = max(mymax, __shfl_xor_sync(0xFFFFFFFFu, mymax, o));
        if (lane == 0) red[wid] = mymax;
        __syncthreads();
        if (tid == 0) {
            uint32_t mm = red[0];
            for (int w = 1; w < NWARP; ++w) mm = max(mm, red[w]);
            red[16] = mm;
        }
        __syncthreads();

        uint32_t lo = 0u, hi = red[16];
        T = 0u;
        int bestGe = NN;
        for (int it = 0; it < 34 && lo <= hi; ++it) {
            uint32_t t = lo + ((hi - lo) >> 1);
            int c = 0;
            for (int i = tid; i < NV4; i += NT) {
                uint4 v = srow[i];
                c += (v.x >= t) + (v.y >= t) + (v.z >= t) + (v.w >= t);
            }
            #pragma unroll
            for (int o = 16; o; o >>= 1) c += __shfl_down_sync(0xFFFFFFFFu, c, o);
            __syncthreads();
            if (lane == 0) red[wid] = (uint32_t)c;
            __syncthreads();
            if (tid == 0) {
                int s = 0;
                for (int w = 0; w < NWARP; ++w) s += (int)red[w];
                red[17] = (uint32_t)s;
            }
            __syncthreads();
            int ge = (int)red[17];
            if (ge >= KTOP) {
                if (ge < bestGe) { bestGe = ge; T = t; }
                if (ge <= CAP) break;
                lo = t + 1;
            } else {
                if (t == 0) break;
                hi = t - 1;
            }
        }

        __syncthreads();
        if (tid == 0) scnt = 0;
        __syncthreads();
        for (int i = tid; i < NV4; i += NT) {
            uint4 v = srow[i];
            if (max(max(v.x, v.y), max(v.z, v.w)) >= T) {
                uint32_t vals[4] = {v.x, v.y, v.z, v.w};
                #pragma unroll
                for (int j = 0; j < 4; ++j) {
                    if (vals[j] >= T) {
                        int p = atomicAdd(&scnt, 1);
                        if (p < CAP) cand[p] = mk_key(vals[j], (uint32_t)(4 * i + j));
                    }
                }
            }
        }
        __syncthreads();
        M = min(scnt, CAP);
    }

    // ---------------- 3. Counting sort (exact, guarded) ------------------------
    // 3a. count
    for (int i = tid; i < M; i += NT) {
        uint32_t v = (uint32_t)(cand[i] >> 32);
        atomicAdd(&counts[bucket_of(v)], 1u);
    }
    __syncthreads();

    // 3b. per-thread chunk sum + max; block max guard
    const int basek = tid * BPT;
    uint32_t csum = 0u, cmax = 0u;
    #pragma unroll
    for (int t = 0; t < BPT; ++t) {
        uint32_t c = counts[basek + t];
        csum += c;
        cmax = max(cmax, c);
    }
    #pragma unroll
    for (int o = 16; o; o >>= 1)
        cmax = max(cmax, __shfl_xor_sync(0xFFFFFFFFu, cmax, o));
    if (lane == 0) red[wid] = cmax;
    __syncthreads();
    if (tid == 0) {
        uint32_t mm = red[0];
        for (int w = 1; w < NWARP; ++w) mm = max(mm, red[w]);
        red[16] = mm;
    }
    __syncthreads();
    const bool bucket_ok = (red[16] <= 8u);
    __syncthreads();

    unsigned long long* sorted;
    if (bucket_ok) {
        // 3c. exclusive block scan of per-thread sums
        uint32_t incl = csum;
        #pragma unroll
        for (int o = 1; o < 32; o <<= 1) {
            uint32_t t = __shfl_up_sync(0xFFFFFFFFu, incl, o);
            if (lane >= o) incl += t;
        }
        uint32_t wex = incl - csum;              // exclusive within warp
        if (lane == 31) red[8 + wid] = incl;     // warp totals
        __syncthreads();
        if (tid == 0) {
            uint32_t run = 0u;
            for (int w = 0; w < NWARP; ++w) {
                uint32_t t = red[8 + w];
                red[8 + w] = run;
                run += t;
            }
        }
        __syncthreads();
        uint32_t tex = red[8 + wid] + wex;       // thread's exclusive base

        // 3d. write back bucket start offsets (counts -> fill pointers)
        uint32_t run = tex;
        #pragma unroll
        for (int t = 0; t < BPT; ++t) {
            uint32_t c = counts[basek + t];
            counts[basek + t] = run;
            run += c;
        }
        __syncthreads();

        // 3e. stable scatter
        for (int i = tid; i < M; i += NT) {
            unsigned long long key = cand[i];
            int bkt = bucket_of((uint32_t)(key >> 32));
            uint32_t pos = atomicAdd(&counts[bkt], 1u);
            dst[pos] = key;
        }
        for (int i = M + tid; i < CAP; i += NT) dst[i] = 0ull;   // pad tail
        __syncthreads();

        // 3f. 8 odd-even cleanup passes: disorder confined to <=8-wide buckets,
        // full (val, ~idx) comparator -> exact descending order incl. ties
        #pragma unroll 1
        for (int p = 0; p < 8; ++p) {
            int l = 2 * tid + (p & 1);
            int r = l + 1;
            if (r < CAP) {
                unsigned long long a = dst[l];
                unsigned long long c2 = dst[r];
                if (a < c2) { dst[l] = c2; dst[r] = a; }
            }
            __syncthreads();
        }
        sorted = dst;
    } else {
        // guarded fallback: full smem bitonic (rare/never)
        for (int i = M + tid; i < CAP; i += NT) cand[i] = 0ull;
        __syncthreads();
        #pragma unroll 1
        for (int k = 2; k <= CAP; k <<= 1) {
            #pragma unroll 1
            for (int j = k >> 1; j > 0; j >>= 1) {
                int i   = 2 * tid - (tid & (j - 1));
                int ixj = i + j;
                unsigned long long a  = cand[i];
                unsigned long long c2 = cand[ixj];
                bool desc = ((i & k) == 0);
                if ((a < c2) == desc) { cand[i] = c2; cand[ixj] = a; }
                __syncthreads();
            }
        }
        sorted = cand;
    }

    // ---------------- 4. Gather + decode boxes ---------------------------------
    float x1 = 0.f, y1v = 0.f, x2 = 0.f, y2v = 0.f, sc = 0.f;
    if (tid < KTOP) {
        unsigned long long key = sorted[tid];
        uint32_t idx = 0xFFFFFFFFu - (uint32_t)(key & 0xFFFFFFFFull);
        sc = __uint_as_float((uint32_t)(key >> 32));
        float4 rb = __ldg(reinterpret_cast<const float4*>(boxes_raw) + (size_t)b * NN + idx);
        float w  = rb.z * 0.5f + 1e-2f;
        float h  = rb.w * 0.5f + 1e-2f;
        float hw = 0.5f * w, hh = 0.5f * h;
        x1  = rb.x - hw;  x2  = rb.x + hw;
        y1v = rb.y - hh;  y2v = rb.y + hh;
        sboxv[tid] = make_float4(x1, y1v, x2, y2v);
        sar[tid]   = (x2 - x1) * (y2v - y1v);    // area from corners (match ref)
    }
    __syncthreads();

    // ---------------- 5. Warp-balanced division-free suppression ---------------
    // iou <= 0.5  <=>  2*inter <= union  <=>  3*inter <= area_i + area_j
    for (int j = wid; j < KTOP; j += NWARP) {
        float4 bj = sboxv[j];
        float  aj = sar[j];
        bool sup = false;
        for (int i = lane; i < j; i += 32) {
            float4 bi = sboxv[i];
            float iw = fminf(bj.z, bi.z) - fmaxf(bj.x, bi.x);
            float ih = fminf(bj.w, bi.w) - fmaxf(bj.y, bi.y);
            iw = fmaxf(iw, 0.f);
            ih = fmaxf(ih, 0.f);
            sup = sup || (3.0f * (iw * ih) > aj + sar[i]);
        }
        sup = __any_sync(0xFFFFFFFFu, sup);
        if (lane == 0) keepf[j] = sup ? 0u : 1u;
    }
    __syncthreads();                             // guards cand reuse below

    // ---------------- 6. Stage + coalesced output write ------------------------
    float* stage = reinterpret_cast<float*>(cand);   // 4KB >= 200*5*4B
    if (tid < KTOP) {
        float osc = (keepf[tid] && sc > 0.05f) ? sc : 0.f;
        stage[tid * 5 + 0] = osc;
        stage[tid * 5 + 1] = x1;
        stage[tid * 5 + 2] = y1v;
        stage[tid * 5 + 3] = x2;
        stage[tid * 5 + 4] = y2v;
    }
    __syncthreads();

    {   // 1000 floats = 250 uint4 per row
        uint4* dstg = reinterpret_cast<uint4*>(out + (size_t)bc * (KTOP * 5));
        const uint4* srcg = reinterpret_cast<const uint4*>(stage);
        if (tid < 250) dstg[tid] = srcg[tid];
    }
}

extern "C" void kernel_launch(void* const* d_in, const int* in_sizes, int n_in,
                              void* d_out, int out_size)
{
    const float* boxes  = (const float*)d_in[0];
    const float* scores = (const float*)d_in[1];
    if (n_in >= 2 && in_sizes[0] > in_sizes[1]) {   // defensive order check
        boxes  = (const float*)d_in[1];
        scores = (const float*)d_in[0];
    }
    (void)out_size;
    fastnms_kernel<<<NB * NC, NT>>>(boxes, scores, (float*)d_out);
}